// round 16
// baseline (speedup 1.0000x reference)
#include <cuda_runtime.h>
#include <cuda_fp16.h>
#include <math_constants.h>

#define N_NODES 50000
#define N_EDGES 800000
#define IN_F 128
#define HF    128   // HEADS * OUT_F
#define HEADS 4
#define NEG_SLOPE 0.2f
#define EPSF 1e-8f

#define SCAN_B 1024
#define N_SCAN_BLOCKS ((N_NODES + SCAN_B - 1) / SCAN_B)   // 49

// smem strides (halves) for mma tiles: 136 = 17*8 -> conflict-free ldmatrix
#define SB_STRIDE 136
#define SA_STRIDE 136
#define SB_BYTES (128 * SB_STRIDE * 2)        // 34816
#define SA_BYTES (64  * SA_STRIDE * 2)        // 17408
#define GEMM_SMEM (SB_BYTES + SA_BYTES)       // 52224

// ---------------- scratch (static device globals; no allocations) -------------
__device__ __align__(16) __half g_h[N_NODES * HF];        // 12.8 MB (fp16)
__device__ __align__(16) __half g_Wth[IN_F * HF];          // W^T fp16 (k-major)
__device__ __align__(16) float g_waS[IN_F * HEADS];        // W^T a_src  (k-major)
__device__ __align__(16) float g_waD[IN_F * HEADS];        // W^T a_dst
__device__ __align__(16) float g_asrc[N_NODES * HEADS];
__device__ __align__(16) float g_adst[N_NODES * HEADS];
__device__ __align__(8) int2 g_edges[N_EDGES];            // packed (src,dst)
__device__ int  g_cnt[N_NODES];                           // per-dst degree
__device__ int  g_fill[N_NODES];                          // scatter cursors
__device__ int  g_off[N_NODES + 1];                       // CSR offsets
__device__ int  g_bsum[N_SCAN_BLOCKS];                    // per-block totals
__device__ int  g_csr_src[N_EDGES];                       // src sorted by dst
__device__ int  g_is64;                                   // dtype flag

__device__ __forceinline__ int clampN(int v) {
    v = v < 0 ? 0 : v;
    return v >= N_NODES ? N_NODES - 1 : v;
}

// ---------------- kernel 0: zero counters + dtype detect (block 0) -------------
__global__ void k_zero_detect(const void* __restrict__ ei) {
    int i = blockIdx.x * 256 + threadIdx.x;
    if (i < N_NODES) g_cnt[i] = 0;
    if (blockIdx.x == 0 && threadIdx.x < 32) {
        const long long* p = (const long long*)ei;
        int lane = threadIdx.x;
        unsigned hi = 0;
        #pragma unroll
        for (int k = 0; k < 4; ++k)
            hi |= (unsigned)((unsigned long long)p[lane * 4 + k] >> 32);
        unsigned any = __ballot_sync(0xffffffffu, hi != 0);
        if (lane == 0) g_is64 = (any == 0);
    }
}

// ---------------- kernel 0b: pack edges + histogram dst -----------------------
__global__ void k_pack(const void* __restrict__ ei) {
    int e = blockIdx.x * 256 + threadIdx.x;
    if (e >= N_EDGES) return;
    int src, dst;
    if (g_is64) {
        src = (int)((const long long*)ei)[e];
        dst = (int)((const long long*)ei)[N_EDGES + e];
    } else {
        src = ((const int*)ei)[e];
        dst = ((const int*)ei)[N_EDGES + e];
    }
    src = clampN(src); dst = clampN(dst);
    g_edges[e] = make_int2(src, dst);
    atomicAdd(&g_cnt[dst], 1);
}

// ---------------- scan stage 1 -------------------------------------------------
__global__ void __launch_bounds__(SCAN_B) k_scan1() {
    __shared__ int wsum[32];
    int t = threadIdx.x;
    int i = blockIdx.x * SCAN_B + t;
    int v = (i < N_NODES) ? g_cnt[i] : 0;

    int lane = t & 31, warp = t >> 5;
    int s = v;
    #pragma unroll
    for (int off = 1; off < 32; off <<= 1) {
        int u = __shfl_up_sync(0xffffffffu, s, off);
        if (lane >= off) s += u;
    }
    if (lane == 31) wsum[warp] = s;
    __syncthreads();
    if (warp == 0) {
        int ws = wsum[lane];
        #pragma unroll
        for (int off = 1; off < 32; off <<= 1) {
            int u = __shfl_up_sync(0xffffffffu, ws, off);
            if (lane >= off) ws += u;
        }
        wsum[lane] = ws;
    }
    __syncthreads();
    int base = warp ? wsum[warp - 1] : 0;
    int excl = base + s - v;
    if (i < N_NODES) g_off[i] = excl;
    if (t == SCAN_B - 1) g_bsum[blockIdx.x] = base + s;
}

// ---------------- scan stage 2 -------------------------------------------------
__global__ void k_scan2() {
    __shared__ int sm[N_SCAN_BLOCKS];
    int t = threadIdx.x;
    if (t < N_SCAN_BLOCKS) sm[t] = g_bsum[t];
    __syncthreads();
    if (t == 0) {
        int run = 0;
        for (int i = 0; i < N_SCAN_BLOCKS; ++i) {
            int c = sm[i]; sm[i] = run; run += c;
        }
        g_off[N_NODES] = N_EDGES;
    }
    __syncthreads();
    if (t < N_SCAN_BLOCKS) g_bsum[t] = sm[t];
}

// ---------------- scan stage 3 -------------------------------------------------
__global__ void __launch_bounds__(SCAN_B) k_scan3() {
    int i = blockIdx.x * SCAN_B + threadIdx.x;
    if (i < N_NODES) {
        int o = g_off[i] + g_bsum[blockIdx.x];
        g_off[i] = o;
        g_fill[i] = o;
    }
}

// ---------------- scatter ------------------------------------------------------
__global__ void k_scatter() {
    int e = blockIdx.x * 256 + threadIdx.x;
    if (e >= N_EDGES) return;
    int2 ed = g_edges[e];
    int pos = atomicAdd(&g_fill[ed.y], 1);
    g_csr_src[pos] = ed.x;
}

// ---------------- k_prep: W^T fp16 + wa = W^T a (fp32) -------------------------
__global__ void k_prep(const float* __restrict__ W,
                       const float* __restrict__ a_src,
                       const float* __restrict__ a_dst) {
    int b = blockIdx.x, t = threadIdx.x;
    if (b < 64) {
        int idx = b * 256 + t;                 // 16384 elems
        int k = idx >> 7, j = idx & 127;
        g_Wth[k * HF + j] = __float2half(W[j * IN_F + k]);
    } else {
        // wa[k][h] = sum_f W[(h*32+f)*128 + k] * a[h*32+f]
        for (int idx = t; idx < 1024; idx += 256) {
            int k = idx & 127;
            int h = (idx >> 7) & 3;
            int sel = idx >> 9;
            const float* a = sel ? a_dst : a_src;
            float acc = 0.f;
            #pragma unroll 8
            for (int f = 0; f < 32; ++f)
                acc += W[(h * 32 + f) * IN_F + k] * a[h * 32 + f];
            (sel ? g_waD : g_waS)[k * HEADS + h] = acc;
        }
    }
}

// ---------------- k_gemm_mma: h = x @ W^T via fp16 mma.sync --------------------
// block: 64 rows x 128 cols; 8 warps: (w&3) -> 16-row stripe, (w>>2) -> 64-col half
extern __shared__ __align__(16) char dynsmem[];

__global__ void __launch_bounds__(256, 2) k_gemm_mma(const float* __restrict__ x) {
    __half* sB = (__half*)dynsmem;                    // [128][SB_STRIDE]
    __half* sA = (__half*)(dynsmem + SB_BYTES);       // [64][SA_STRIDE]

    int tid = threadIdx.x;
    int n0 = blockIdx.x * 64;

    // load W^T (whole 128x128) into sB
    #pragma unroll
    for (int i = 0; i < 16; ++i) {
        int idx = tid + i * 256;                      // 4096 uint2 groups
        int k = idx >> 5, jq = idx & 31;
        uint2 v = *(const uint2*)&g_Wth[k * HF + jq * 4];
        *(uint2*)&sB[k * SB_STRIDE + jq * 4] = v;
    }
    // load x tile (64 x 128) fp32 -> fp16
    #pragma unroll
    for (int i = 0; i < 8; ++i) {
        int idx = tid + i * 256;                      // 2048 float4 groups
        int n = idx >> 5, kq = idx & 31;
        int gn = n0 + n;
        float4 v = make_float4(0.f, 0.f, 0.f, 0.f);
        if (gn < N_NODES) v = *(const float4*)&x[(size_t)gn * IN_F + kq * 4];
        __half2 lo = __floats2half2_rn(v.x, v.y);
        __half2 hi = __floats2half2_rn(v.z, v.w);
        uint2 pk = make_uint2(*(unsigned*)&lo, *(unsigned*)&hi);
        *(uint2*)&sA[n * SA_STRIDE + kq * 4] = pk;
    }
    __syncthreads();

    int w = tid >> 5, l = tid & 31;
    int wr = (w & 3) * 16;           // row offset
    int wc = (w >> 2) * 64;          // col offset

    float c[8][4];
    #pragma unroll
    for (int t = 0; t < 8; ++t)
        #pragma unroll
        for (int i = 0; i < 4; ++i) c[t][i] = 0.f;

    unsigned saAddr = (unsigned)__cvta_generic_to_shared(sA);
    unsigned sbAddr = (unsigned)__cvta_generic_to_shared(sB);
    unsigned aBase = saAddr + ((wr + (l & 15)) * SA_STRIDE + 8 * (l >> 4)) * 2;
    unsigned bBase = sbAddr + ((l & 15) * SB_STRIDE + wc) * 2;

    #pragma unroll
    for (int ks = 0; ks < 8; ++ks) {
        unsigned a0, a1, a2, a3;
        asm volatile("ldmatrix.sync.aligned.m8n8.x4.shared.b16 {%0,%1,%2,%3}, [%4];"
                     : "=r"(a0), "=r"(a1), "=r"(a2), "=r"(a3)
                     : "r"(aBase + ks * 32));
        unsigned bRow = bBase + ks * (16 * SB_STRIDE * 2);
        #pragma unroll
        for (int t = 0; t < 8; ++t) {
            unsigned b0, b1;
            asm volatile("ldmatrix.sync.aligned.m8n8.x2.trans.shared.b16 {%0,%1}, [%2];"
                         : "=r"(b0), "=r"(b1)
                         : "r"(bRow + t * 16));
            asm volatile("mma.sync.aligned.m16n8k16.row.col.f32.f16.f16.f32 "
                         "{%0,%1,%2,%3}, {%4,%5,%6,%7}, {%8,%9}, {%0,%1,%2,%3};"
                         : "+f"(c[t][0]), "+f"(c[t][1]), "+f"(c[t][2]), "+f"(c[t][3])
                         : "r"(a0), "r"(a1), "r"(a2), "r"(a3), "r"(b0), "r"(b1));
        }
    }

    // epilogue: write h fp16
    int tg = l >> 2, t4 = l & 3;
    int row0 = n0 + wr + tg;
    int row1 = row0 + 8;
    #pragma unroll
    for (int t = 0; t < 8; ++t) {
        int col = wc + 8 * t + 2 * t4;
        if (row0 < N_NODES)
            *(__half2*)&g_h[(size_t)row0 * HF + col] = __floats2half2_rn(c[t][0], c[t][1]);
        if (row1 < N_NODES)
            *(__half2*)&g_h[(size_t)row1 * HF + col] = __floats2half2_rn(c[t][2], c[t][3]);
    }
}

// ---------------- k_alpha: alpha = x @ wa (fp32, warp per node) ----------------
__global__ void __launch_bounds__(256) k_alpha(const float* __restrict__ x) {
    int w = threadIdx.x >> 5, l = threadIdx.x & 31;
    int n = blockIdx.x * 8 + w;
    if (n >= N_NODES) return;

    // this lane's 4 k-values: k = 4l+c
    float wS[4][4], wD[4][4];
    #pragma unroll
    for (int cc = 0; cc < 4; ++cc) {
        float4 vs = *(const float4*)&g_waS[(4 * l + cc) * HEADS];
        float4 vd = *(const float4*)&g_waD[(4 * l + cc) * HEADS];
        wS[cc][0] = vs.x; wS[cc][1] = vs.y; wS[cc][2] = vs.z; wS[cc][3] = vs.w;
        wD[cc][0] = vd.x; wD[cc][1] = vd.y; wD[cc][2] = vd.z; wD[cc][3] = vd.w;
    }

    float4 xv = *(const float4*)&x[(size_t)n * IN_F + l * 4];
    float xa[4] = {xv.x, xv.y, xv.z, xv.w};

    float ps[4] = {0.f, 0.f, 0.f, 0.f}, pd[4] = {0.f, 0.f, 0.f, 0.f};
    #pragma unroll
    for (int cc = 0; cc < 4; ++cc)
        #pragma unroll
        for (int h = 0; h < 4; ++h) {
            ps[h] += xa[cc] * wS[cc][h];
            pd[h] += xa[cc] * wD[cc][h];
        }

    #pragma unroll
    for (int off = 16; off > 0; off >>= 1)
        #pragma unroll
        for (int h = 0; h < 4; ++h) {
            ps[h] += __shfl_xor_sync(0xffffffffu, ps[h], off);
            pd[h] += __shfl_xor_sync(0xffffffffu, pd[h], off);
        }

    if (l == 0) {
        *(float4*)&g_asrc[n * HEADS] = make_float4(ps[0], ps[1], ps[2], ps[3]);
        *(float4*)&g_adst[n * HEADS] = make_float4(pd[0], pd[1], pd[2], pd[3]);
    }
}

// ---------------- kernel 3: CSR aggregation (warp per dst node) ----------------
#define CHUNK 64
__global__ void __launch_bounds__(256) k_agg(float* __restrict__ out) {
    __shared__ float4 sh_exp[8][CHUNK];
    __shared__ int    sh_src[8][CHUNK];

    int w    = threadIdx.x >> 5;
    int lane = threadIdx.x & 31;
    int n    = blockIdx.x * 8 + w;
    if (n >= N_NODES) return;

    int start = g_off[n];
    int end   = g_off[n + 1];

    int e2 = lane >> 4;          // edge slot within pair (0/1)
    int q  = lane & 15;          // feature octet
    int headq = q >> 2;

    float acc[8] = {0.f, 0.f, 0.f, 0.f, 0.f, 0.f, 0.f, 0.f};
    float4 sum = make_float4(0.f, 0.f, 0.f, 0.f);

    if (start < end) {
        float4 b4 = *(const float4*)&g_adst[n * HEADS];

        for (int cs = start; cs < end; cs += CHUNK) {
            int cnt = min(end - cs, CHUNK);
            for (int k = lane; k < cnt; k += 32) {
                int src = g_csr_src[cs + k];
                float4 a = *(const float4*)&g_asrc[src * HEADS];
                float v0 = a.x + b4.x, v1 = a.y + b4.y;
                float v2 = a.z + b4.z, v3 = a.w + b4.w;
                v0 = v0 > 0.f ? v0 : NEG_SLOPE * v0;
                v1 = v1 > 0.f ? v1 : NEG_SLOPE * v1;
                v2 = v2 > 0.f ? v2 : NEG_SLOPE * v2;
                v3 = v3 > 0.f ? v3 : NEG_SLOPE * v3;
                float4 ex = make_float4(__expf(v0), __expf(v1), __expf(v2), __expf(v3));
                sh_exp[w][k] = ex;
                sh_src[w][k] = src;
                sum.x += ex.x; sum.y += ex.y; sum.z += ex.z; sum.w += ex.w;
            }
            if (lane == 0 && (cnt & 1)) {
                sh_exp[w][cnt] = make_float4(0.f, 0.f, 0.f, 0.f);
                sh_src[w][cnt] = sh_src[w][0];
            }
            __syncwarp();
            int cnt2 = (cnt + 1) & ~1;
            #pragma unroll 4
            for (int k = 0; k < cnt2; k += 2) {
                int kk = k + e2;
                float att = ((const float*)&sh_exp[w][kk])[headq];
                int src = sh_src[w][kk];
                uint4 pk = *(const uint4*)&g_h[(size_t)src * HF + q * 8];
                float2 f0 = __half22float2(*(const __half2*)&pk.x);
                float2 f1 = __half22float2(*(const __half2*)&pk.y);
                float2 f2 = __half22float2(*(const __half2*)&pk.z);
                float2 f3 = __half22float2(*(const __half2*)&pk.w);
                acc[0] += att * f0.x; acc[1] += att * f0.y;
                acc[2] += att * f1.x; acc[3] += att * f1.y;
                acc[4] += att * f2.x; acc[5] += att * f2.y;
                acc[6] += att * f3.x; acc[7] += att * f3.y;
            }
            __syncwarp();
        }

        #pragma unroll
        for (int j = 0; j < 8; ++j)
            acc[j] += __shfl_xor_sync(0xffffffffu, acc[j], 16);

        #pragma unroll
        for (int off = 1; off < 32; off <<= 1) {
            sum.x += __shfl_xor_sync(0xffffffffu, sum.x, off);
            sum.y += __shfl_xor_sync(0xffffffffu, sum.y, off);
            sum.z += __shfl_xor_sync(0xffffffffu, sum.z, off);
            sum.w += __shfl_xor_sync(0xffffffffu, sum.w, off);
        }
        float sh = ((const float*)&sum)[headq];
        float inv = 1.f / (sh + EPSF);
        #pragma unroll
        for (int j = 0; j < 8; ++j) acc[j] *= inv;
    }

    if (e2 == 0) {
        float4 o0 = make_float4(acc[0], acc[1], acc[2], acc[3]);
        float4 o1 = make_float4(acc[4], acc[5], acc[6], acc[7]);
        *(float4*)&out[(size_t)n * HF + q * 8]     = o0;
        *(float4*)&out[(size_t)n * HF + q * 8 + 4] = o1;
    }
}

// ---------------- launch (fork/join; gemm is 6th launch for ncu) ---------------
extern "C" void kernel_launch(void* const* d_in, const int* in_sizes, int n_in,
                              void* d_out, int out_size) {
    const float* x     = (const float*)d_in[0];
    const void*  ei    = d_in[1];
    const float* W     = (const float*)d_in[2];
    const float* a_src = (const float*)d_in[3];
    const float* a_dst = (const float*)d_in[4];
    float*       out   = (float*)d_out;

    static cudaStream_t sA = nullptr;
    static cudaEvent_t  evFork = nullptr, evJoin = nullptr;
    if (!sA) {
        cudaStreamCreateWithFlags(&sA, cudaStreamNonBlocking);
        cudaEventCreateWithFlags(&evFork, cudaEventDisableTiming);
        cudaEventCreateWithFlags(&evJoin, cudaEventDisableTiming);
        cudaFuncSetAttribute(k_gemm_mma, cudaFuncAttributeMaxDynamicSharedMemorySize,
                             GEMM_SMEM);
    }

    cudaEventRecord(evFork, 0);
    cudaStreamWaitEvent(sA, evFork, 0);

    // interleaved submission: k_gemm_mma is the 6th kernel launch (ncu -s 5)
    k_prep<<<65, 256>>>(W, a_src, a_dst);                               // 1 (B)
    k_zero_detect<<<(N_NODES + 255) / 256, 256, 0, sA>>>(ei);           // 2 (A)
    k_pack<<<(N_EDGES + 255) / 256, 256, 0, sA>>>(ei);                  // 3 (A)
    k_scan1<<<N_SCAN_BLOCKS, SCAN_B, 0, sA>>>();                        // 4 (A)
    k_scan2<<<1, 64, 0, sA>>>();                                        // 5 (A)
    k_gemm_mma<<<(N_NODES + 63) / 64, 256, GEMM_SMEM>>>(x);             // 6 (B)
    k_alpha<<<(N_NODES + 7) / 8, 256>>>(x);                             // 7 (B)
    k_scan3<<<N_SCAN_BLOCKS, SCAN_B, 0, sA>>>();                        // 8 (A)
    k_scatter<<<(N_EDGES + 255) / 256, 256, 0, sA>>>();                 // 9 (A)
    cudaEventRecord(evJoin, sA);

    cudaStreamWaitEvent(0, evJoin, 0);
    k_agg<<<(N_NODES + 7) / 8, 256>>>(out);                             // 10
}